// round 7
// baseline (speedup 1.0000x reference)
#include <cuda_runtime.h>
#include <cstdint>

// FPS on GB300, round 6: "flat" pipeline — no intra-CTA barriers in the loop.
//   each warp: update -> warp REDUX -> lane0 publishes warp candidate
//              {v,gidx,x,y,z} via st.cluster into hub(CTA0) slot[rank*16+warp]
//              -> mbarrier.arrive.release.cluster on LOCAL ctambar
//   warp0/CTA: waits ctambar (16 warps), forwards ONE release-arrive to hub
//              mbar (avoids 256-way arrive serialization)
//   hub (CTA0 warp0): waits 16 arrivals, reduces 256 candidates (8/lane
//              serial + REDUX pair), broadcasts winner xyz + release-arrive
//              to every CTA's resmbar
//   all warps: HW-sleep try_wait(parity) on local resmbar, read winner (LDS).
// Visibility: st.cluster -> arrive.release.cluster(local) -> warp0
// try_wait.acquire -> arrive.release.cluster(hub) -> hub try_wait.acquire
// (transitive happens-before); hub st.cluster res -> arrive.release ->
// spoke try_wait.acquire.
// WAR: slots double-buffered by parity; hub reads slot_p(s) before res(s);
// spokes write slot_p(s+2) only after res(s+1). res single-buffered: hub
// writes res(s+1) only after all warps of every CTA arrived (s+1), each after
// data-dependent read of res(s).

#define NPTS     131072
#define BATCH    8
#define NSAMP    4096
#define NT       512
#define NW       (NT / 32)
#define BIGF     1e10f

#define ADD2(o, a, b) asm("add.rn.f32x2 %0, %1, %2;" : "=l"(o) : "l"(a), "l"(b))
#define MUL2(o, a, b) asm("mul.rn.f32x2 %0, %1, %2;" : "=l"(o) : "l"(a), "l"(b))
#define PACK2(o, lo, hi) asm("mov.b64 %0, {%1, %2};" : "=l"(o) : "f"(lo), "f"(hi))
#define UNPACK2(lo, hi, in) asm("mov.b64 {%0, %1}, %2;" : "=f"(lo), "=f"(hi) : "l"(in))

static __device__ __forceinline__ uint32_t smem_u32(const void* p) {
    uint32_t a;
    asm("{ .reg .u64 t; cvta.to.shared.u64 t, %1; cvt.u32.u64 %0, t; }"
        : "=r"(a) : "l"(p));
    return a;
}
static __device__ __forceinline__ uint32_t mapa_rank(uint32_t local, uint32_t rank) {
    uint32_t r;
    asm("mapa.shared::cluster.u32 %0, %1, %2;" : "=r"(r) : "r"(local), "r"(rank));
    return r;
}
static __device__ __forceinline__ void st_cluster_b64(uint32_t addr, unsigned long long v) {
    asm volatile("st.shared::cluster.b64 [%0], %1;" :: "r"(addr), "l"(v) : "memory");
}
static __device__ __forceinline__ void st_cluster_b32(uint32_t addr, uint32_t v) {
    asm volatile("st.shared::cluster.b32 [%0], %1;" :: "r"(addr), "r"(v) : "memory");
}
// release-arrive on a LOCAL mbarrier, cluster scope.
static __device__ __forceinline__ void mbar_arrive_local_release(uint32_t mbar) {
    asm volatile("mbarrier.arrive.release.cluster.shared::cta.b64 _, [%0];"
                 :: "r"(mbar) : "memory");
}
// release-arrive on a REMOTE (mapa'd) mbarrier, cluster scope.
static __device__ __forceinline__ void mbar_arrive_remote_release(uint32_t rmbar) {
    asm volatile("mbarrier.arrive.release.cluster.shared::cluster.b64 _, [%0];"
                 :: "r"(rmbar) : "memory");
}
// HW-sleep wait on phase parity (acquire, cluster scope), with tick hint.
static __device__ __forceinline__ void mbar_wait_parity(uint32_t mbar, uint32_t parity) {
    asm volatile(
        "{\n\t"
        ".reg .pred P;\n\t"
        "WL_%=:\n\t"
        "mbarrier.try_wait.parity.acquire.cluster.shared::cta.b64 P, [%0], %1, 0x989680;\n\t"
        "@!P bra WL_%=;\n\t"
        "}" :: "r"(mbar), "r"(parity) : "memory");
}
static __device__ __forceinline__ unsigned long long f2_to_u64(float a, float b) {
    unsigned long long r;
    asm("mov.b64 %0, {%1, %2};" : "=l"(r) : "f"(a), "f"(b));
    return r;
}
static __device__ __forceinline__ void cluster_barrier() {
    asm volatile("barrier.cluster.arrive.aligned;" ::: "memory");
    asm volatile("barrier.cluster.wait.aligned;" ::: "memory");
}

template <int CS, bool REGC>
__device__ __forceinline__ void fps_body(const float* __restrict__ pts,
                                         float* __restrict__ out)
{
    constexpr int PPC    = NPTS / CS;
    constexpr int QPT    = PPC / (4 * NT);
    constexpr int LOGPPC = (CS == 16) ? 13 : 14;
    constexpr int SLOTS  = CS * NW;          // warp-level candidates cluster-wide
    constexpr int SPL    = SLOTS / 32;       // slots per hub lane

    extern __shared__ float sm[];
    float* smx   = sm;
    float* smy   = sm + PPC;
    float* smz   = sm + 2 * PPC;
    float* slots = sm + 3 * PPC;             // [2][SLOTS][8] floats (32B stride)
    float* res   = slots + 2 * SLOTS * 8;    // [4] winner xyz
    unsigned long long* ctambar = (unsigned long long*)(res + 4);
    unsigned long long* hubmbar = ctambar + 1;
    unsigned long long* resmbar = ctambar + 2;

    const int tid  = threadIdx.x;
    const int lane = tid & 31;
    const int warp = tid >> 5;
    uint32_t rank;
    asm("mov.u32 %0, %%cluster_ctarank;" : "=r"(rank));
    const int b = blockIdx.x / CS;
    const float* P = pts + (size_t)b * NPTS * 3;
    const int base = (int)rank * PPC;

    // Load coords: SMEM SoA copy (winner xyz lookup) + f32x2 register cache.
    unsigned long long Xr[REGC ? 2 * QPT : 1];
    unsigned long long Yr[REGC ? 2 * QPT : 1];
    unsigned long long Zr[REGC ? 2 * QPT : 1];
#pragma unroll
    for (int j = 0; j < QPT; j++) {
        const int i0 = 4 * (j * NT + tid);
        float x[4], y[4], z[4];
#pragma unroll
        for (int k = 0; k < 4; k++) {
            const float* g = P + (size_t)(base + i0 + k) * 3;
            x[k] = g[0]; y[k] = g[1]; z[k] = g[2];
            smx[i0 + k] = x[k]; smy[i0 + k] = y[k]; smz[i0 + k] = z[k];
        }
        if (REGC) {
            PACK2(Xr[2 * j], x[0], x[1]); PACK2(Xr[2 * j + 1], x[2], x[3]);
            PACK2(Yr[2 * j], y[0], y[1]); PACK2(Yr[2 * j + 1], y[2], y[3]);
            PACK2(Zr[2 * j], z[0], z[1]); PACK2(Zr[2 * j + 1], z[2], z[3]);
        }
    }

    const uint32_t ctambar_u32 = smem_u32(ctambar);
    const uint32_t hubmbar_u32 = smem_u32(hubmbar);
    const uint32_t resmbar_u32 = smem_u32(resmbar);
    const uint32_t slots_u32   = smem_u32(slots);
    if (tid == 0) {
        asm volatile("mbarrier.init.shared.b64 [%0], %1;"
                     :: "r"(ctambar_u32), "r"((unsigned)NW) : "memory");
        asm volatile("mbarrier.init.shared.b64 [%0], %1;"
                     :: "r"(hubmbar_u32), "r"((unsigned)CS) : "memory");
        asm volatile("mbarrier.init.shared.b64 [%0], %1;"
                     :: "r"(resmbar_u32), "r"(1u) : "memory");
    }

    float4 md[QPT];
#pragma unroll
    for (int j = 0; j < QPT; j++) md[j] = make_float4(BIGF, BIGF, BIGF, BIGF);

    __syncthreads();
    cluster_barrier();   // publish smem coords + mbarrier inits cluster-wide

    float lx = P[0], ly = P[1], lz = P[2];   // reference: last_idx init = 0

    // Hoisted addresses.
    // This warp's candidate slot in the hub (CTA0), phase 0.
    const uint32_t hub_slot0 =
        mapa_rank(slots_u32 + (uint32_t)(rank * NW + warp) * 32u, 0u);
    const uint32_t hub_slot1 = hub_slot0 + (uint32_t)(SLOTS * 32);
    const uint32_t hub_mbar_remote = mapa_rank(hubmbar_u32, 0u);   // for warp0
    // Hub broadcast targets (warp0-of-CTA0 lanes < CS).
    const uint32_t tgt = (uint32_t)(lane < CS ? lane : 0);
    const uint32_t sp_res  = mapa_rank(smem_u32(res), tgt);
    const uint32_t sp_mbar = mapa_rank(resmbar_u32, tgt);

    for (int s = 0; s < NSAMP; s++) {
        const uint32_t p = (uint32_t)(s & 1);

        // Reference scan emits last_idx BEFORE the update.
        if (rank == 0 && tid == 0) {
            float* o = out + ((size_t)b * NSAMP + s) * 3;
            o[0] = lx; o[1] = ly; o[2] = lz;
        }

        unsigned long long NX, NY, NZ;
        {
            float nx = -lx, ny = -ly, nz = -lz;  // x + (-l) == x - l bit-exact
            PACK2(NX, nx, nx); PACK2(NY, ny, ny); PACK2(NZ, nz, nz);
        }

        // ---- distance update (packed f32x2; mul-then-add order = reference) ----
#pragma unroll
        for (int j = 0; j < QPT; j++) {
            unsigned long long xa, xb, ya, yb, za, zb;
            if (REGC) {
                xa = Xr[2 * j]; xb = Xr[2 * j + 1];
                ya = Yr[2 * j]; yb = Yr[2 * j + 1];
                za = Zr[2 * j]; zb = Zr[2 * j + 1];
            } else {
                const int q4 = j * NT + tid;
                float4 X = ((const float4*)smx)[q4];
                float4 Y = ((const float4*)smy)[q4];
                float4 Z = ((const float4*)smz)[q4];
                PACK2(xa, X.x, X.y); PACK2(xb, X.z, X.w);
                PACK2(ya, Y.x, Y.y); PACK2(yb, Y.z, Y.w);
                PACK2(za, Z.x, Z.y); PACK2(zb, Z.z, Z.w);
            }
            unsigned long long sa, sb;
            ADD2(xa, xa, NX); MUL2(xa, xa, xa);
            ADD2(ya, ya, NY); MUL2(ya, ya, ya);
            ADD2(za, za, NZ); MUL2(za, za, za);
            ADD2(sa, xa, ya);
            ADD2(sa, sa, za);
            ADD2(xb, xb, NX); MUL2(xb, xb, xb);
            ADD2(yb, yb, NY); MUL2(yb, yb, yb);
            ADD2(zb, zb, NZ); MUL2(zb, zb, zb);
            ADD2(sb, xb, yb);
            ADD2(sb, sb, zb);
            float d0, d1, d2, d3;
            UNPACK2(d0, d1, sa);
            UNPACK2(d2, d3, sb);
            md[j].x = fminf(md[j].x, d0);
            md[j].y = fminf(md[j].y, d1);
            md[j].z = fminf(md[j].z, d2);
            md[j].w = fminf(md[j].w, d3);
        }

        // ---- thread-local argmax (lowest index wins on ties) ----
        float bestv = md[0].x;
#pragma unroll
        for (int j = 0; j < QPT; j++) {
            bestv = fmaxf(fmaxf(bestv, fmaxf(md[j].x, md[j].y)),
                          fmaxf(md[j].z, md[j].w));
        }
        int besti = 0;
#pragma unroll
        for (int j = QPT - 1; j >= 0; j--) {
            const int ib = 4 * (j * NT + tid);
            if (md[j].w == bestv) besti = ib + 3;
            if (md[j].z == bestv) besti = ib + 2;
            if (md[j].y == bestv) besti = ib + 1;
            if (md[j].x == bestv) besti = ib + 0;
        }

        // ---- warp reduce (REDUX max bits / min idx among holders) ----
        unsigned vb   = __float_as_uint(bestv);
        unsigned wmax = __reduce_max_sync(0xffffffffu, vb);
        unsigned imin = __reduce_min_sync(0xffffffffu,
                                          vb == wmax ? (unsigned)besti : 0xffffffffu);

        // ---- per-warp publish to hub + local aggregate arrive ----
        if (lane == 0) {
            float cx = smx[imin], cy = smy[imin], cz = smz[imin];
            unsigned gi = (unsigned)(base + (int)imin);
            uint32_t dst = p ? hub_slot1 : hub_slot0;
            st_cluster_b64(dst,
                           (unsigned long long)wmax | ((unsigned long long)gi << 32));
            st_cluster_b64(dst + 8, f2_to_u64(cx, cy));
            st_cluster_b32(dst + 16, __float_as_uint(cz));
            mbar_arrive_local_release(ctambar_u32);
        }

        // ---- warp0: aggregate this CTA's 16 warps, forward one arrive ----
        if (warp == 0) {
            if (lane == 0) {
                mbar_wait_parity(ctambar_u32, p);
                mbar_arrive_remote_release(hub_mbar_remote);
            }
            // ---- hub: CTA0 warp0 collects + reduces + broadcasts ----
            if (rank == 0) {
                if (lane == 0) mbar_wait_parity(hubmbar_u32, p);
                __syncwarp(0xffffffffu);

                // Each lane scans SPL slots serially (u32-compare on nonneg
                // fp32 bits; lowest gidx wins ties).
                unsigned bv = 0u, bi = 0xffffffffu;
                float bx = 0.f, by = 0.f, bz = 0.f;
                const float* sl0 = slots + (p * SLOTS + lane * SPL) * 8;
#pragma unroll
                for (int k = 0; k < SPL; k++) {
                    const float* sl = sl0 + k * 8;
                    unsigned v  = ((const unsigned*)sl)[0];
                    unsigned gi = ((const unsigned*)sl)[1];
                    if (v > bv || (v == bv && gi < bi)) {
                        bv = v; bi = gi;
                        bx = sl[2]; by = sl[3]; bz = sl[4];
                    }
                }
                unsigned gmax = __reduce_max_sync(0xffffffffu, bv);
                unsigned gsel = __reduce_min_sync(
                    0xffffffffu, bv == gmax ? bi : 0xffffffffu);
                unsigned ball = __ballot_sync(0xffffffffu,
                                              bv == gmax && bi == gsel);
                const int src = __ffs(ball) - 1;
                bx = __shfl_sync(0xffffffffu, bx, src);
                by = __shfl_sync(0xffffffffu, by, src);
                bz = __shfl_sync(0xffffffffu, bz, src);
                if (lane < CS) {
                    st_cluster_b64(sp_res, f2_to_u64(bx, by));
                    st_cluster_b32(sp_res + 8, __float_as_uint(bz));
                    mbar_arrive_remote_release(sp_mbar);
                }
            }
        }

        // ---- all warps: sleep until the winner lands, then read it ----
        mbar_wait_parity(resmbar_u32, p);
        lx = res[0]; ly = res[1]; lz = res[2];
    }
}

__global__ void __cluster_dims__(16, 1, 1) __launch_bounds__(NT, 1)
fps16(const float* __restrict__ pts, float* __restrict__ out) {
    fps_body<16, true>(pts, out);
}
__global__ void __cluster_dims__(8, 1, 1) __launch_bounds__(NT, 1)
fps8(const float* __restrict__ pts, float* __restrict__ out) {
    fps_body<8, false>(pts, out);
}

static size_t smem_bytes(int cs) {
    int ppc = NPTS / cs;
    int slots = cs * NW;
    return (size_t)(3 * ppc + 2 * slots * 8 + 4 + 8) * sizeof(float);
}

extern "C" void kernel_launch(void* const* d_in, const int* in_sizes, int n_in,
                              void* d_out, int out_size)
{
    (void)in_sizes; (void)n_in; (void)out_size;
    const float* pts = (const float*)d_in[0];   // point_coord (8, 131072, 3)
    float* out = (float*)d_out;                 // (8, 4096, 3)

    const size_t s16 = smem_bytes(16);
    const size_t s8  = smem_bytes(8);

    cudaFuncSetAttribute(fps16, cudaFuncAttributeNonPortableClusterSizeAllowed, 1);
    cudaFuncSetAttribute(fps16, cudaFuncAttributeMaxDynamicSharedMemorySize, (int)s16);
    cudaFuncSetAttribute(fps8,  cudaFuncAttributeMaxDynamicSharedMemorySize, (int)s8);
    cudaGetLastError();

    int nc = 0;
    cudaLaunchConfig_t cfg = {};
    cfg.gridDim  = dim3(BATCH * 16, 1, 1);
    cfg.blockDim = dim3(NT, 1, 1);
    cfg.dynamicSmemBytes = s16;
    cudaLaunchAttribute at[1];
    at[0].id = cudaLaunchAttributeClusterDimension;
    at[0].val.clusterDim.x = 16;
    at[0].val.clusterDim.y = 1;
    at[0].val.clusterDim.z = 1;
    cfg.attrs = at;
    cfg.numAttrs = 1;
    cudaError_t e = cudaOccupancyMaxActiveClusters(&nc, fps16, &cfg);

    if (e == cudaSuccess && nc > 0) {
        fps16<<<BATCH * 16, NT, s16>>>(pts, out);
    } else {
        cudaGetLastError();
        fps8<<<BATCH * 8, NT, s8>>>(pts, out);
    }
}

// round 8
// speedup vs baseline: 2.9344x; 2.9344x over previous
#include <cuda_runtime.h>
#include <cstdint>

// FPS on GB300, round 7: exchange through L2 instead of DSMEM; no clusters.
// Grid: 128 plain CTAs, 16 per batch (group = blockIdx.x/16, rank = %16).
// Coords register-resident (R3 compute path, bit-exact f32x2 math).
// Per step:
//   warps: update -> warp REDUX -> wv/wi -> __syncthreads
//   warp0: CTA REDUX -> lane0 publishes {x,y | z,v | (s+1)<<32|gi} to
//          g_ex[group][rank] via st.relaxed.gpu x2 + st.release.gpu (tag)
//          -> lanes<16 poll peers' tags (ld.acquire.gpu, ~260cyc natural
//          backoff), read payloads (ld.relaxed.gpu, L1-coherent), REDUX pair,
//          ballot/shfl winner xyz -> res smem
//   all  : bar.sync 1 (park, proven R5), read winner from smem.
// WAR: tag(s)=s+1 monotone; any CTA writes slot(s+1) only after it read all
// tags(s), and readers of (s) pass their poll before publishing (s+1), so a
// slot is never overwritten before all 16 peers consumed it... (overwrite at
// s+1 races only with readers still at s, who then see tag s+2!=s+1 and keep
// polling until... readers at s want tag s+1 exactly; writer's next write is
// s+2 only after its own poll of s+1 passed, which needs THIS reader's
// publish(s+1), which follows its read(s). Chain closed.)
// Cross-run staleness: slots persist across graph replays; a stale tag can
// only equal the wanted value for the same step of the previous run, whose
// payload bytes are identical (kernel is deterministic). Tags are re-zeroed
// at launch anyway.

#define NPTS   131072
#define BATCH  8
#define NSAMP  4096
#define GRP    16
#define NT     512
#define PPC    (NPTS / GRP)          // 8192
#define QPT    (PPC / (4 * NT))      // 4
#define BIGF   1e10f

// L2 exchange slots: [batch][rank] = {xy, zv, tag|gi, pad} (32B per slot).
__device__ unsigned long long g_ex[BATCH][GRP][4];

#define ADD2(o, a, b) asm("add.rn.f32x2 %0, %1, %2;" : "=l"(o) : "l"(a), "l"(b))
#define MUL2(o, a, b) asm("mul.rn.f32x2 %0, %1, %2;" : "=l"(o) : "l"(a), "l"(b))
#define PACK2(o, lo, hi) asm("mov.b64 %0, {%1, %2};" : "=l"(o) : "f"(lo), "f"(hi))
#define UNPACK2(lo, hi, in) asm("mov.b64 {%0, %1}, %2;" : "=f"(lo), "=f"(hi) : "l"(in))

static __device__ __forceinline__ void st_rlx_gpu(unsigned long long* p,
                                                  unsigned long long v) {
    asm volatile("st.relaxed.gpu.global.u64 [%0], %1;" :: "l"(p), "l"(v) : "memory");
}
static __device__ __forceinline__ void st_rel_gpu(unsigned long long* p,
                                                  unsigned long long v) {
    asm volatile("st.release.gpu.global.u64 [%0], %1;" :: "l"(p), "l"(v) : "memory");
}
static __device__ __forceinline__ unsigned long long ld_acq_gpu(
    const unsigned long long* p) {
    unsigned long long v;
    asm volatile("ld.acquire.gpu.global.u64 %0, [%1];" : "=l"(v) : "l"(p) : "memory");
    return v;
}
static __device__ __forceinline__ unsigned long long ld_rlx_gpu(
    const unsigned long long* p) {
    unsigned long long v;
    asm volatile("ld.relaxed.gpu.global.u64 %0, [%1];" : "=l"(v) : "l"(p) : "memory");
    return v;
}
static __device__ __forceinline__ unsigned long long f2_to_u64(float a, float b) {
    unsigned long long r;
    asm("mov.b64 %0, {%1, %2};" : "=l"(r) : "f"(a), "f"(b));
    return r;
}
static __device__ __forceinline__ void named_bar(int id, int count) {
    asm volatile("bar.sync %0, %1;" :: "r"(id), "r"(count) : "memory");
}

__global__ void __launch_bounds__(NT, 1)
fps_l2(const float* __restrict__ pts, float* __restrict__ out)
{
    extern __shared__ float sm[];
    float*    smx = sm;                     // [PPC]
    float*    smy = sm + PPC;
    float*    smz = sm + 2 * PPC;
    unsigned* wv  = (unsigned*)(sm + 3 * PPC);   // [32] warp best value bits
    unsigned* wi  = wv + 32;                     // [32] warp best local idx
    float*    res = (float*)(wi + 32);           // [4] winner xyz

    const int tid  = threadIdx.x;
    const int lane = tid & 31;
    const int warp = tid >> 5;
    const int g    = blockIdx.x >> 4;       // batch
    const int rank = blockIdx.x & 15;
    const float* P = pts + (size_t)g * NPTS * 3;
    const int base = rank * PPC;

    // Zero my tag slot (hygiene; correctness holds even without, see header).
    if (tid == 0) st_rlx_gpu(&g_ex[g][rank][2], 0ull);

    // Load this CTA's coords: SMEM SoA (winner-xyz lookup) + f32x2 reg cache.
    unsigned long long Xr[2 * QPT], Yr[2 * QPT], Zr[2 * QPT];
#pragma unroll
    for (int j = 0; j < QPT; j++) {
        const int i0 = 4 * (j * NT + tid);
        float x[4], y[4], z[4];
#pragma unroll
        for (int k = 0; k < 4; k++) {
            const float* gp = P + (size_t)(base + i0 + k) * 3;
            x[k] = gp[0]; y[k] = gp[1]; z[k] = gp[2];
            smx[i0 + k] = x[k]; smy[i0 + k] = y[k]; smz[i0 + k] = z[k];
        }
        PACK2(Xr[2 * j], x[0], x[1]); PACK2(Xr[2 * j + 1], x[2], x[3]);
        PACK2(Yr[2 * j], y[0], y[1]); PACK2(Yr[2 * j + 1], y[2], y[3]);
        PACK2(Zr[2 * j], z[0], z[1]); PACK2(Zr[2 * j + 1], z[2], z[3]);
    }
    if (tid < 32) { wv[tid] = 0u; wi[tid] = 0xffffffffu; }  // pad lanes 16..31

    float4 md[QPT];
#pragma unroll
    for (int j = 0; j < QPT; j++) md[j] = make_float4(BIGF, BIGF, BIGF, BIGF);

    __syncthreads();

    float lx = P[0], ly = P[1], lz = P[2];   // reference: last_idx init = 0

    for (int s = 0; s < NSAMP; s++) {
        // Reference scan emits last_idx BEFORE the update.
        if (rank == 0 && tid == 0) {
            float* o = out + ((size_t)g * NSAMP + s) * 3;
            o[0] = lx; o[1] = ly; o[2] = lz;
        }

        unsigned long long NX, NY, NZ;
        {
            float nx = -lx, ny = -ly, nz = -lz;  // x + (-l) == x - l bit-exact
            PACK2(NX, nx, nx); PACK2(NY, ny, ny); PACK2(NZ, nz, nz);
        }

        // ---- distance update (packed f32x2; mul-then-add order = reference) ----
#pragma unroll
        for (int j = 0; j < QPT; j++) {
            unsigned long long xa = Xr[2 * j], xb = Xr[2 * j + 1];
            unsigned long long ya = Yr[2 * j], yb = Yr[2 * j + 1];
            unsigned long long za = Zr[2 * j], zb = Zr[2 * j + 1];
            unsigned long long sa, sb;
            ADD2(xa, xa, NX); MUL2(xa, xa, xa);
            ADD2(ya, ya, NY); MUL2(ya, ya, ya);
            ADD2(za, za, NZ); MUL2(za, za, za);
            ADD2(sa, xa, ya);          // (dx^2 + dy^2)
            ADD2(sa, sa, za);          // + dz^2 — same order as jnp.sum
            ADD2(xb, xb, NX); MUL2(xb, xb, xb);
            ADD2(yb, yb, NY); MUL2(yb, yb, yb);
            ADD2(zb, zb, NZ); MUL2(zb, zb, zb);
            ADD2(sb, xb, yb);
            ADD2(sb, sb, zb);
            float d0, d1, d2, d3;
            UNPACK2(d0, d1, sa);
            UNPACK2(d2, d3, sb);
            md[j].x = fminf(md[j].x, d0);
            md[j].y = fminf(md[j].y, d1);
            md[j].z = fminf(md[j].z, d2);
            md[j].w = fminf(md[j].w, d3);
        }

        // ---- thread-local argmax (lowest index wins on ties) ----
        float bestv = md[0].x;
#pragma unroll
        for (int j = 0; j < QPT; j++) {
            bestv = fmaxf(fmaxf(bestv, fmaxf(md[j].x, md[j].y)),
                          fmaxf(md[j].z, md[j].w));
        }
        int besti = 0;
#pragma unroll
        for (int j = QPT - 1; j >= 0; j--) {
            const int ib = 4 * (j * NT + tid);
            if (md[j].w == bestv) besti = ib + 3;
            if (md[j].z == bestv) besti = ib + 2;
            if (md[j].y == bestv) besti = ib + 1;
            if (md[j].x == bestv) besti = ib + 0;
        }

        // ---- warp reduce (REDUX max bits / min idx among holders) ----
        unsigned vb   = __float_as_uint(bestv);
        unsigned wmax = __reduce_max_sync(0xffffffffu, vb);
        unsigned imin = __reduce_min_sync(0xffffffffu,
                                          vb == wmax ? (unsigned)besti : 0xffffffffu);
        if (lane == 0) { wv[warp] = wmax; wi[warp] = imin; }
        __syncthreads();

        if (warp == 0) {
            // ---- CTA reduce ----
            unsigned v2   = wv[lane];
            unsigned i2   = wi[lane];
            unsigned cmax = __reduce_max_sync(0xffffffffu, v2);
            unsigned csel = __reduce_min_sync(0xffffffffu,
                                              v2 == cmax ? i2 : 0xffffffffu);
            // ---- publish to L2: payload (relaxed) then tag (release) ----
            if (lane == 0) {
                float cx = smx[csel], cy = smy[csel], cz = smz[csel];
                unsigned gi = (unsigned)(base + (int)csel);
                unsigned long long* slot = &g_ex[g][rank][0];
                st_rlx_gpu(&slot[0], f2_to_u64(cx, cy));
                st_rlx_gpu(&slot[1], f2_to_u64(cz, __uint_as_float(cmax)));
                st_rel_gpu(&slot[2],
                           ((unsigned long long)(unsigned)(s + 1) << 32) | gi);
            }
            // ---- poll all 16 peer tags (lanes<16; whole warp loops) ----
            const unsigned long long want = (unsigned long long)(unsigned)(s + 1);
            unsigned long long t = 0;
            const unsigned long long* peer =
                &g_ex[g][lane < GRP ? lane : 0][0];
            bool ok;
            do {
                if (lane < GRP) t = ld_acq_gpu(&peer[2]);
                ok = (lane >= GRP) || ((t >> 32) == want);
            } while (!__all_sync(0xffffffffu, ok));

            // ---- group reduce over 16 candidates ----
            unsigned gv = 0u, ggi = 0xffffffffu;
            float gx = 0.f, gy = 0.f, gz = 0.f;
            if (lane < GRP) {
                unsigned long long xy = ld_rlx_gpu(&peer[0]);
                unsigned long long zv = ld_rlx_gpu(&peer[1]);
                float fv;
                UNPACK2(gx, gy, xy);
                UNPACK2(gz, fv, zv);
                gv  = __float_as_uint(fv);
                ggi = (unsigned)t;
            }
            unsigned gmax = __reduce_max_sync(0xffffffffu, gv);
            unsigned gsel = __reduce_min_sync(
                0xffffffffu, (lane < GRP && gv == gmax) ? ggi : 0xffffffffu);
            unsigned ball = __ballot_sync(0xffffffffu,
                                          lane < GRP && gv == gmax && ggi == gsel);
            const int src = __ffs(ball) - 1;
            gx = __shfl_sync(0xffffffffu, gx, src);
            gy = __shfl_sync(0xffffffffu, gy, src);
            gz = __shfl_sync(0xffffffffu, gz, src);
            if (lane == 0) { res[0] = gx; res[1] = gy; res[2] = gz; }
        }

        // ---- release all warps; read winner (broadcast LDS) ----
        named_bar(1, NT);
        lx = res[0]; ly = res[1]; lz = res[2];
    }
}

extern "C" void kernel_launch(void* const* d_in, const int* in_sizes, int n_in,
                              void* d_out, int out_size)
{
    (void)in_sizes; (void)n_in; (void)out_size;
    const float* pts = (const float*)d_in[0];   // point_coord (8, 131072, 3)
    float* out = (float*)d_out;                 // (8, 4096, 3)

    const size_t smem = (size_t)(3 * PPC + 64 + 4) * sizeof(float);
    cudaFuncSetAttribute(fps_l2, cudaFuncAttributeMaxDynamicSharedMemorySize,
                         (int)smem);
    fps_l2<<<BATCH * GRP, NT, smem>>>(pts, out);
}